// round 14
// baseline (speedup 1.0000x reference)
#include <cuda_runtime.h>

// CausalGraphGenerator: the reference builds A = diag(v) per batch, so
// A_diff = A - A^T == 0 exactly (off-diag entries are v*0.0f; on-diag
// subtract bitwise-identical values). Therefore
//   adj[b,i,j] = (i==j) ? 0.0f : max(-h, 0.0f)
// Output [B=4, C=64, C=64] fp32 = 16384 elements = 64 KB.
//
// Launch-shape experiment: one warp per CTA, 128 CTAs (one per SM, single
// wave on 148 SMs). Each warp issues exactly one STG.128 and exits —
// minimal per-SM work, no intra-CTA warp queueing. Lane 0 of each CTA loads
// h; only in the h < 0 case (never for this dataset, but required for
// input-faithfulness) does it rewrite its CTA's own 512 B slice.
// Slice-local fixup => no cross-block write races.

static constexpr int C  = 64;        // channels
static constexpr int CC = C * C;     // 4096 elements per batch slab

__global__ void __launch_bounds__(32, 1)
causal_graph_fill_kernel(const float* __restrict__ h_ptr,
                         float* __restrict__ out) {
    const int q = blockIdx.x * 32 + threadIdx.x;   // float4 index; 128*32 = 4096 exactly

    // Phase 1: unconditional zero store — no dependency on h. Bitwise-correct
    // final value for every element when h >= 0.
    reinterpret_cast<float4*>(out)[q] = make_float4(0.0f, 0.0f, 0.0f, 0.0f);

    // Phase 2: lane 0 checks h and, if relu(-h) != 0, rewrites this CTA's
    // own 32-float4 slice with position-determined constants.
    if (threadIdx.x == 0) {
        const float offdiag = fmaxf(-__ldg(h_ptr), 0.0f);
        if (offdiag != 0.0f) {
            __threadfence();   // order after phase-1 zeros
            int base0 = blockIdx.x * 128;          // floats; 32 float4 per CTA
            for (int t = 0; t < 32; ++t) {
                int base = base0 + t * 4;
                int r = base & (CC - 1);
                int i = r >> 6;
                int j = r & (C - 1);
                float4 v;
                v.x = (j + 0 == i) ? 0.0f : offdiag;
                v.y = (j + 1 == i) ? 0.0f : offdiag;
                v.z = (j + 2 == i) ? 0.0f : offdiag;
                v.w = (j + 3 == i) ? 0.0f : offdiag;
                reinterpret_cast<float4*>(out)[base >> 2] = v;
            }
        }
    }
}

extern "C" void kernel_launch(void* const* d_in, const int* in_sizes, int n_in,
                              void* d_out, int out_size) {
    // Inputs (metadata order): X, w1, b1, w2, b2, h
    const float* h_ptr = (const float*)d_in[5];
    float* out = (float*)d_out;

    // out_size = 16384 floats; 128 blocks x 32 threads x float4 covers it exactly.
    causal_graph_fill_kernel<<<128, 32>>>(h_ptr, out);
}

// round 15
// speedup vs baseline: 1.1776x; 1.1776x over previous
#include <cuda_runtime.h>

// CausalGraphGenerator: the reference builds A = diag(v) per batch, so
// A_diff = A - A^T == 0 exactly (off-diag entries are v*0.0f; on-diag
// subtract bitwise-identical values). Therefore
//   adj[b,i,j] = (i==j) ? 0.0f : max(-h, 0.0f)
// Output [B=4, C=64, C=64] fp32 = 16384 elements = 64 KB.
//
// Final structure (best measured, reproduced twice at 4.58/4.61 us):
// 16 CTAs x 256 threads, one float4 zero-store per thread with no load
// dependency; 7 of 8 warps per block exit immediately. One thread per block
// loads h; only in the h < 0 case (never for this dataset, but required for
// input-faithfulness) does it rewrite its block's own 4 KB slice.
// Slice-local fixup => no cross-block write races.
//
// Measured floor: kernel ~4.0 us is invariant across launch shapes and
// instruction schedules (16x256, 128x32, load-hoisted, rolled/unrolled) —
// it is launch/drain overhead (T_ovh), not device work. 128-CTA grids add
// ~1.1 us of harness-visible launch cost; 16 CTAs is the measured optimum.

static constexpr int C  = 64;        // channels
static constexpr int CC = C * C;     // 4096 elements per batch slab

__global__ void __launch_bounds__(256, 1)
causal_graph_fill_kernel(const float* __restrict__ h_ptr,
                         float* __restrict__ out) {
    const int q = blockIdx.x * 256 + threadIdx.x;   // float4 index; grid covers 4096 exactly

    // Phase 1: unconditional zero store — no dependency on h. Bitwise-correct
    // final value for every element when h >= 0.
    reinterpret_cast<float4*>(out)[q] = make_float4(0.0f, 0.0f, 0.0f, 0.0f);

    // Phase 2: one thread per block checks h and, if relu(-h) != 0, rewrites
    // this block's own 256-float4 slice with position-determined constants.
    if (threadIdx.x == 0) {
        const float offdiag = fmaxf(-__ldg(h_ptr), 0.0f);
        if (offdiag != 0.0f) {
            __threadfence();   // order after phase-1 zeros
            int base0 = blockIdx.x * 1024;
            for (int t = 0; t < 256; ++t) {
                int base = base0 + t * 4;
                int r = base & (CC - 1);
                int i = r >> 6;
                int j = r & (C - 1);
                float4 v;
                v.x = (j + 0 == i) ? 0.0f : offdiag;
                v.y = (j + 1 == i) ? 0.0f : offdiag;
                v.z = (j + 2 == i) ? 0.0f : offdiag;
                v.w = (j + 3 == i) ? 0.0f : offdiag;
                reinterpret_cast<float4*>(out)[base >> 2] = v;
            }
        }
    }
}

extern "C" void kernel_launch(void* const* d_in, const int* in_sizes, int n_in,
                              void* d_out, int out_size) {
    // Inputs (metadata order): X, w1, b1, w2, b2, h
    const float* h_ptr = (const float*)d_in[5];
    float* out = (float*)d_out;

    // out_size = 16384 floats; 16 blocks x 256 threads x float4 covers it exactly.
    causal_graph_fill_kernel<<<16, 256>>>(h_ptr, out);
}

// round 16
// speedup vs baseline: 1.1933x; 1.0133x over previous
#include <cuda_runtime.h>

// CausalGraphGenerator: the reference builds A = diag(v) per batch, so
// A_diff = A - A^T == 0 exactly (off-diag entries are v*0.0f; on-diag
// subtract bitwise-identical values). Therefore
//   adj[b,i,j] = (i==j) ? 0.0f : max(-h, 0.0f)
// Output [B=4, C=64, C=64] fp32 = 16384 elements = 64 KB.
//
// Grid-size probe: R14 showed harness-visible launch cost scales with CTA
// count (~10 ns/CTA: 128 CTAs cost +1.1 us vs 16). Halve the grid to 8 CTAs
// x 256 threads, two float4 zero-stores per thread. Kernel-side time is
// T_ovh-bound and should stay flat; the probe targets the launch term only.
// Lane-0-per-block h check + slice-local fixup (8 KB/block) preserves
// input-faithfulness for h < 0 with no cross-block write races.

static constexpr int C  = 64;        // channels
static constexpr int CC = C * C;     // 4096 elements per batch slab

__global__ void __launch_bounds__(256, 1)
causal_graph_fill_kernel(const float* __restrict__ h_ptr,
                         float* __restrict__ out) {
    // 8 blocks x 256 threads x 2 float4 = 4096 float4 = 16384 floats exactly.
    const int q0 = blockIdx.x * 512 + threadIdx.x;         // first float4 index
    const int q1 = q0 + 256;                               // second float4 index

    // Phase 1: unconditional zero stores — no dependency on h. Bitwise-correct
    // final value for every element when h >= 0.
    const float4 z = make_float4(0.0f, 0.0f, 0.0f, 0.0f);
    reinterpret_cast<float4*>(out)[q0] = z;
    reinterpret_cast<float4*>(out)[q1] = z;

    // Phase 2: one thread per block checks h and, if relu(-h) != 0, rewrites
    // this block's own 512-float4 slice with position-determined constants.
    if (threadIdx.x == 0) {
        const float offdiag = fmaxf(-__ldg(h_ptr), 0.0f);
        if (offdiag != 0.0f) {
            __threadfence();   // order after phase-1 zeros
            int base0 = blockIdx.x * 2048;   // floats; 512 float4 per block
            for (int t = 0; t < 512; ++t) {
                int base = base0 + t * 4;
                int r = base & (CC - 1);
                int i = r >> 6;
                int j = r & (C - 1);
                float4 v;
                v.x = (j + 0 == i) ? 0.0f : offdiag;
                v.y = (j + 1 == i) ? 0.0f : offdiag;
                v.z = (j + 2 == i) ? 0.0f : offdiag;
                v.w = (j + 3 == i) ? 0.0f : offdiag;
                reinterpret_cast<float4*>(out)[base >> 2] = v;
            }
        }
    }
}

extern "C" void kernel_launch(void* const* d_in, const int* in_sizes, int n_in,
                              void* d_out, int out_size) {
    // Inputs (metadata order): X, w1, b1, w2, b2, h
    const float* h_ptr = (const float*)d_in[5];
    float* out = (float*)d_out;

    // out_size = 16384 floats; 8 blocks x 256 threads x 2 float4 covers it exactly.
    causal_graph_fill_kernel<<<8, 256>>>(h_ptr, out);
}